// round 6
// baseline (speedup 1.0000x reference)
#include <cuda_runtime.h>
#include <cuda_bf16.h>
#include <cstdint>

// Problem: q [2,1024,128] (rows unit-norm), k [2,1024,128], queue [128,65536] (cols unit-norm)
#define NV 2
#define NN 1024
#define DD 128
#define KK 65536
#define QT 512              // queue tiles of 128 cols
#define TILE_U32 8192       // 32KB bf16 tile image (128 rows x 128 k, swizzled)

// ---------------- scratch (static device globals; no allocation) ----------------
__device__ __align__(128) uint32_t g_qu[QT * TILE_U32];       // queue tile images (16.8MB)
__device__ __align__(128) uint32_t g_qt[NV * 8 * TILE_U32];   // q tile images (512KB)
__device__ float g_EQ[NN], g_WQ[NN];          // queue part: sum e^{-s}, sum d*e^{-s}
__device__ float g_EI[NV * NN], g_WI[NV * NN];
__device__ float g_l1part[128];               // loss1 per-block partials

// ---------------- helpers ----------------
__device__ __forceinline__ uint32_t smem_u32(const void* p) {
    uint32_t a;
    asm("{ .reg .u64 t; cvta.to.shared.u64 t, %1; cvt.u32.u64 %0, t; }" : "=r"(a) : "l"(p));
    return a;
}
__device__ __forceinline__ void cp16(uint32_t daddr, const void* src) {
    asm volatile("cp.async.cg.shared.global [%0], [%1], 16;" :: "r"(daddr), "l"(src));
}
__device__ __forceinline__ void ldsm_x4(uint32_t* r, uint32_t addr) {
    asm volatile("ldmatrix.sync.aligned.m8n8.x4.shared.b16 {%0,%1,%2,%3}, [%4];"
                 : "=r"(r[0]), "=r"(r[1]), "=r"(r[2]), "=r"(r[3]) : "r"(addr));
}
__device__ __forceinline__ void mma_bf16(float* c, const uint32_t* a, const uint32_t* b) {
    asm volatile(
        "mma.sync.aligned.m16n8k16.row.col.f32.bf16.bf16.f32 "
        "{%0,%1,%2,%3}, {%4,%5,%6,%7}, {%8,%9}, {%0,%1,%2,%3};"
        : "+f"(c[0]), "+f"(c[1]), "+f"(c[2]), "+f"(c[3])
        : "r"(a[0]), "r"(a[1]), "r"(a[2]), "r"(a[3]), "r"(b[0]), "r"(b[1]));
}
// first k-step: C = zero registers (separate from D) -> no accumulator rezero needed
__device__ __forceinline__ void mma_bf16_z(float* c, const uint32_t* a, const uint32_t* b,
                                           const float* z) {
    asm volatile(
        "mma.sync.aligned.m16n8k16.row.col.f32.bf16.bf16.f32 "
        "{%0,%1,%2,%3}, {%4,%5,%6,%7}, {%8,%9}, {%10,%11,%12,%13};"
        : "=f"(c[0]), "=f"(c[1]), "=f"(c[2]), "=f"(c[3])
        : "r"(a[0]), "r"(a[1]), "r"(a[2]), "r"(a[3]), "r"(b[0]), "r"(b[1]),
          "f"(z[0]), "f"(z[1]), "f"(z[2]), "f"(z[3]));
}
// swizzled u32 index inside a 128x128 bf16 tile: row stride 256B, 16B chunks XOR (row&7)
__device__ __forceinline__ uint32_t tidx(uint32_t row, uint32_t kp /*k/2*/) {
    return row * 64u + ((((kp >> 2) ^ (row & 7u))) << 2) + (kp & 3u);
}

// ---------------- merged pre-kernel (512 threads/block) ----------------
// blocks 0..511: queue->image | 512..527: q->image | 528..655: loss1 | 656: zero E/W
__global__ __launch_bounds__(512) void pre_kernel(const float* __restrict__ q,
                                                  const float* __restrict__ k,
                                                  const float* __restrict__ queue) {
    const int bid = blockIdx.x, tid = threadIdx.x;
    if (bid < 512) {
        // direct transpose-convert: thread handles one n (0..127) x 16 kp values
        const int t = bid;
        const int n = tid & 127, kseg = tid >> 7;      // kseg 0..3
        const float* qb = queue + (size_t)(kseg * 32) * KK + t * 128 + n;
        uint32_t v[16];
        #pragma unroll
        for (int kk = 0; kk < 16; kk++) {
            float x0 = qb[(size_t)(2 * kk) * KK];
            float x1 = qb[(size_t)(2 * kk + 1) * KK];
            __nv_bfloat162 b = __floats2bfloat162_rn(x0, x1);
            v[kk] = *(uint32_t*)&b;
        }
        uint32_t* dst = g_qu + (size_t)t * TILE_U32;
        #pragma unroll
        for (int c = 0; c < 4; c++) {
            uint32_t i0 = tidx((uint32_t)n, (uint32_t)(kseg * 16 + c * 4));
            *(uint4*)(dst + i0) = make_uint4(v[c * 4], v[c * 4 + 1], v[c * 4 + 2], v[c * 4 + 3]);
        }
    } else if (bid < 528) {
        // q -> bf16 swizzled tile image (tile = v*8+rb), natural [m][k] layout
        const int t = bid - 512;
        const float* src = q + (size_t)t * 128 * DD;
        uint32_t* dst = g_qt + (size_t)t * TILE_U32;
        #pragma unroll
        for (int it = 0; it < 16; it++) {
            int idx = it * 512 + tid;
            int row = idx >> 6, kp = idx & 63;
            float2 v = *(const float2*)(src + row * DD + 2 * kp);
            __nv_bfloat162 b = __floats2bfloat162_rn(v.x, v.y);
            dst[tidx(row, kp)] = *(uint32_t*)&b;
        }
    } else if (bid < 656) {
        // loss1 partial: 16 warps, warp per row; lane holds one float4
        __shared__ float sw[16];
        const int wid = tid >> 5, lane = tid & 31;
        const int w = (bid - 528) * 16 + wid;
        const int x = w >> 10, i = w & (NN - 1);
        float4 a = ((const float4*)(q + ((size_t)x * NN + i) * DD))[lane];
        float4 b = ((const float4*)(k + ((size_t)(1 - x) * NN + i) * DD))[lane];
        float dx = a.x - b.x, dy = a.y - b.y, dz = a.z - b.z, dw = a.w - b.w;
        float s = fmaf(dx, dx, fmaf(dy, dy, fmaf(dz, dz, dw * dw)));
        #pragma unroll
        for (int m = 16; m >= 1; m >>= 1) s += __shfl_xor_sync(0xffffffffu, s, m);
        if (lane == 0) sw[wid] = s;
        __syncthreads();
        if (tid == 0) {
            float acc = 0.f;
            #pragma unroll
            for (int j = 0; j < 16; j++) acc += sw[j];
            g_l1part[bid - 528] = acc;
        }
    } else {
        for (int i = tid; i < NV * NN; i += 512) {
            if (i < NN) { g_EQ[i] = 0.f; g_WQ[i] = 0.f; }
            g_EI[i] = 0.f; g_WI[i] = 0.f;
        }
    }
}

// ---------------- bf16 mma.sync GEMM (512 thr, warp tile 16x32, 2 m-passes) ----------------
// bid < 512: queue part: rows = q[0] block (bid>>6), B tiles = j-group (bid&63)*8
// bid >= 512: intra part: view x, row block rb; B tiles = all 8 tiles of q[x]
__global__ __launch_bounds__(512, 2) void gemm_ws() {
    extern __shared__ __align__(128) char smg[];
    const uint32_t sb = smem_u32(smg);
    const uint32_t o_A = sb, o_B0 = sb + 32768, o_B1 = sb + 65536;
    const int tid = threadIdx.x, lane = tid & 31, wid = tid >> 5;
    const int wm = wid >> 2, wn = wid & 3;        // 4x4 warps, warp tile 16x32 (x2 m-passes)
    const int bid = blockIdx.x;

    const uint32_t *Asrc, *Bsrc;
    float *Eout, *Wout;
    int rowbase;
    if (bid < 512) {
        int rb = bid >> 6, jg = bid & 63;
        Asrc = g_qt + (size_t)rb * TILE_U32;                  // view 0 rows
        Bsrc = g_qu + (size_t)(jg * 8) * TILE_U32;
        Eout = g_EQ; Wout = g_WQ; rowbase = rb * 128;
    } else {
        int id = bid - 512, x = id >> 3, rb = id & 7;
        Asrc = g_qt + (size_t)(x * 8 + rb) * TILE_U32;
        Bsrc = g_qt + (size_t)(x * 8) * TILE_U32;
        Eout = g_EI + x * NN; Wout = g_WI + x * NN; rowbase = rb * 128;
    }

    // prologue: A + B0 (contiguous 32KB copies), one commit group
    #pragma unroll
    for (int c = 0; c < 4; c++) cp16(o_A + (c * 512 + tid) * 16, Asrc + (c * 512 + tid) * 4);
    #pragma unroll
    for (int c = 0; c < 4; c++) cp16(o_B0 + (c * 512 + tid) * 16, Bsrc + (c * 512 + tid) * 4);
    asm volatile("cp.async.commit_group;");

    // per-lane ldmatrix address components (same verified pattern as before)
    const uint32_t swz = (uint32_t)(lane & 7);
    const uint32_t hiA = (uint32_t)(lane >> 4);
    const uint32_t baseA = o_A + (uint32_t)(wm * 16 + (lane & 15)) * 256u;   // + h*64 rows
    const uint32_t nrowb = (uint32_t)(wn * 32 + ((lane >> 4) & 1) * 8 + (lane & 7));
    const uint32_t kbB = (uint32_t)((lane >> 3) & 1);

    float E[4] = {0.f, 0.f, 0.f, 0.f}, W[4] = {0.f, 0.f, 0.f, 0.f};
    const float zc[4] = {0.f, 0.f, 0.f, 0.f};

    for (int t = 0; t < 8; t++) {
        const int buf = t & 1;
        if (t < 7) {          // prefetch next B into the other buffer
            uint32_t dstB = buf ? o_B0 : o_B1;
            const uint32_t* s = Bsrc + (size_t)(t + 1) * TILE_U32;
            #pragma unroll
            for (int c = 0; c < 4; c++) cp16(dstB + (c * 512 + tid) * 16, s + (c * 512 + tid) * 4);
            asm volatile("cp.async.commit_group;");
            asm volatile("cp.async.wait_group 1;");
        } else {
            asm volatile("cp.async.wait_group 0;");
        }
        __syncthreads();      // current B visible to all warps

        const uint32_t Brow = (buf ? o_B1 : o_B0) + nrowb * 256u;
        #pragma unroll
        for (int h = 0; h < 2; h++) {          // two 64-row m-passes
            float acc[16];
            #pragma unroll
            for (int ks = 0; ks < 8; ks++) {
                uint32_t a[4];
                ldsm_x4(a, baseA + (uint32_t)(h * 16384)
                           + (((2u * (uint32_t)ks + hiA) ^ swz) << 4));
                uint32_t offB = (((2u * (uint32_t)ks + kbB) ^ swz) << 4);
                #pragma unroll
                for (int p = 0; p < 2; p++) {
                    uint32_t bb[4];
                    ldsm_x4(bb, Brow + (uint32_t)(p * 4096) + offB);
                    if (ks == 0) {
                        mma_bf16_z(&acc[p * 8],     a, bb,     zc);
                        mma_bf16_z(&acc[p * 8 + 4], a, bb + 2, zc);
                    } else {
                        mma_bf16(&acc[p * 8],     a, bb);
                        mma_bf16(&acc[p * 8 + 4], a, bb + 2);
                    }
                }
            }
            // fused epilogue: w = e^{2d-2}; E += w; W += d*w
            #pragma unroll
            for (int f = 0; f < 16; f++) {
                float d = acc[f];
                float e2 = fmaf(d, 2.885390082f, -2.885390082f);   // (2d-2)*log2(e)
                float w; asm("ex2.approx.f32 %0, %1;" : "=f"(w) : "f"(e2));
                int ri = 2 * h + ((f & 3) >> 1);
                E[ri] += w; W[ri] = fmaf(d, w, W[ri]);
            }
        }
        __syncthreads();      // all warps done reading B[t] before overwrite
    }

    // reduce over the 4 lanes sharing each row, then atomics
    #pragma unroll
    for (int m = 1; m < 4; m <<= 1)
        #pragma unroll
        for (int ri = 0; ri < 4; ri++) {
            E[ri] += __shfl_xor_sync(0xffffffffu, E[ri], m);
            W[ri] += __shfl_xor_sync(0xffffffffu, W[ri], m);
        }
    if ((lane & 3) == 0) {
        int g = lane >> 2;
        #pragma unroll
        for (int h = 0; h < 2; h++)
            #pragma unroll
            for (int hh = 0; hh < 2; hh++) {
                int row = rowbase + h * 64 + wm * 16 + hh * 8 + g;
                atomicAdd(&Eout[row], E[2 * h + hh]);
                atomicAdd(&Wout[row], W[2 * h + hh]);
            }
    }
}

__global__ void finalize_kernel(float* __restrict__ out) {
    int i = threadIdx.x;   // 1024 threads
    float v = 0.f;
    #pragma unroll
    for (int x = 0; x < NV; x++) {
        float S  = g_EQ[i] + g_EI[x * NN + i];   // sum e^{-s} incl. diagonal (=1)
        float Wt = g_WQ[i] + g_WI[x * NN + i];   // sum d*e^{-s}
        float T = 2.f * (S - Wt);                // sum s*e^{-s} (diag adds 0)
        float E = S - 1.f;                       // drop diagonal
        v -= T / E;
    }
    float l1 = (i < 128) ? g_l1part[i] : 0.f;
    __shared__ float r2[32], r1[32];
    #pragma unroll
    for (int m = 16; m >= 1; m >>= 1) {
        v  += __shfl_xor_sync(0xffffffffu, v, m);
        l1 += __shfl_xor_sync(0xffffffffu, l1, m);
    }
    if ((i & 31) == 0) { r2[i >> 5] = v; r1[i >> 5] = l1; }
    __syncthreads();
    if (i < 32) {
        float w = r2[i], u = r1[i];
        #pragma unroll
        for (int m = 16; m >= 1; m >>= 1) {
            w += __shfl_xor_sync(0xffffffffu, w, m);
            u += __shfl_xor_sync(0xffffffffu, u, m);
        }
        if (i == 0) {
            out[0] = u * (1.0f / (NV * NN));
            out[1] = w * (1.0f / (NV * NN));
        }
    }
}

// ---------------- launcher ----------------
extern "C" void kernel_launch(void* const* d_in, const int* in_sizes, int n_in,
                              void* d_out, int out_size) {
    const float* q     = (const float*)d_in[0];
    const float* k     = (const float*)d_in[1];
    const float* queue = (const float*)d_in[2];
    float* out = (float*)d_out;

    const int smem_gemm = 3 * 32768;              // A + B double buffer = 96KB
    cudaFuncSetAttribute(gemm_ws, cudaFuncAttributeMaxDynamicSharedMemorySize, smem_gemm);

    pre_kernel<<<657, 512>>>(q, k, queue);
    gemm_ws<<<512 + 16, 512, smem_gemm>>>();
    finalize_kernel<<<1, 1024>>>(out);
}

// round 7
// speedup vs baseline: 2.0577x; 2.0577x over previous
#include <cuda_runtime.h>
#include <cuda_bf16.h>
#include <cstdint>

// Problem: q [2,1024,128] (rows unit-norm), k [2,1024,128], queue [128,65536] (cols unit-norm)
#define NV 2
#define NN 1024
#define DD 128
#define KK 65536
#define QT 512              // queue tiles of 128 cols
#define TILE_U32 8192       // 32KB bf16 tile image (128 rows x 128 k, swizzled)

// ---------------- scratch (static device globals; no allocation) ----------------
__device__ __align__(128) uint32_t g_qu[QT * TILE_U32];       // queue tile images (16.8MB)
__device__ __align__(128) uint32_t g_qt[NV * 8 * TILE_U32];   // q tile images (512KB)
__device__ float g_EQ[NN], g_WQ[NN];          // queue part: sum e^{-s}, sum d*e^{-s}
__device__ float g_EI[NV * NN], g_WI[NV * NN];
__device__ float g_l1part[128];               // loss1 per-block partials

// ---------------- helpers ----------------
__device__ __forceinline__ uint32_t smem_u32(const void* p) {
    uint32_t a;
    asm("{ .reg .u64 t; cvta.to.shared.u64 t, %1; cvt.u32.u64 %0, t; }" : "=r"(a) : "l"(p));
    return a;
}
__device__ __forceinline__ void cp16(uint32_t daddr, const void* src) {
    asm volatile("cp.async.cg.shared.global [%0], [%1], 16;" :: "r"(daddr), "l"(src));
}
__device__ __forceinline__ void ldsm_x4(uint32_t* r, uint32_t addr) {
    asm volatile("ldmatrix.sync.aligned.m8n8.x4.shared.b16 {%0,%1,%2,%3}, [%4];"
                 : "=r"(r[0]), "=r"(r[1]), "=r"(r[2]), "=r"(r[3]) : "r"(addr));
}
__device__ __forceinline__ void mma_bf16(float* c, const uint32_t* a, const uint32_t* b) {
    asm volatile(
        "mma.sync.aligned.m16n8k16.row.col.f32.bf16.bf16.f32 "
        "{%0,%1,%2,%3}, {%4,%5,%6,%7}, {%8,%9}, {%0,%1,%2,%3};"
        : "+f"(c[0]), "+f"(c[1]), "+f"(c[2]), "+f"(c[3])
        : "r"(a[0]), "r"(a[1]), "r"(a[2]), "r"(a[3]), "r"(b[0]), "r"(b[1]));
}
// swizzled u32 index inside a 128x128 bf16 tile: row stride 256B, 16B chunks XOR (row&7)
__device__ __forceinline__ uint32_t tidx(uint32_t row, uint32_t kp /*k/2*/) {
    return row * 64u + ((((kp >> 2) ^ (row & 7u))) << 2) + (kp & 3u);
}

// epilogue of 4 accumulator elements (2 f16x2 ex2 pairs): w=e^{2d-2}; E+=w; W+=d*w; rezero
__device__ __forceinline__ void epi4(float* acc, int f0, float* E, float* W) {
    #pragma unroll
    for (int u = 0; u < 4; u += 2) {
        int f = f0 + u;
        float d0 = acc[f], d1 = acc[f + 1];
        acc[f] = 0.f; acc[f + 1] = 0.f;
        float e0 = fmaf(d0, 2.885390082f, -2.885390082f);   // (2d-2)*log2(e)
        float e1 = fmaf(d1, 2.885390082f, -2.885390082f);
        uint32_t hp;
        asm("cvt.rn.f16x2.f32 %0, %1, %2;" : "=r"(hp) : "f"(e1), "f"(e0));  // lo=e0, hi=e1
        asm("ex2.approx.f16x2 %0, %0;" : "+r"(hp));
        float w0, w1;
        asm("{ .reg .b16 l, h;\n\t mov.b32 {l, h}, %2;\n\t"
            "cvt.f32.f16 %0, l;\n\t cvt.f32.f16 %1, h; }"
            : "=f"(w0), "=f"(w1) : "r"(hp));
        int ri = ((f >> 4) << 1) + ((f & 3) >> 1);          // f and f+1 share ri
        E[ri] += w0 + w1;
        W[ri] = fmaf(d0, w0, fmaf(d1, w1, W[ri]));
    }
}

// MMA over one 32-col half (PBASE = 0 or 2), interleaving the epilogue of the OTHER half
template <int PBASE, bool DOEPI>
__device__ __forceinline__ void half_mma(uint32_t baseA0, uint32_t baseA1, uint32_t Brow,
                                         uint32_t hiA, uint32_t swz, uint32_t kbB,
                                         float* acc, float* oacc, float* E, float* W) {
    #pragma unroll
    for (int ks = 0; ks < 8; ks++) {
        uint32_t a0[4], a1[4];
        uint32_t offA = (((2u * (uint32_t)ks + hiA) ^ swz) << 4);
        ldsm_x4(a0, baseA0 + offA);
        ldsm_x4(a1, baseA1 + offA);
        uint32_t offB = (((2u * (uint32_t)ks + kbB) ^ swz) << 4);
        #pragma unroll
        for (int pp = 0; pp < 2; pp++) {
            uint32_t bb[4];
            ldsm_x4(bb, Brow + (uint32_t)((PBASE + pp) * 4096) + offB);
            mma_bf16(&acc[(2 * pp) * 4],          a0, bb);
            mma_bf16(&acc[(2 * pp + 1) * 4],      a0, bb + 2);
            mma_bf16(&acc[16 + (2 * pp) * 4],     a1, bb);
            mma_bf16(&acc[16 + (2 * pp + 1) * 4], a1, bb + 2);
        }
        if (DOEPI) epi4(oacc, ks * 4, E, W);
    }
}

// ---------------- merged pre-kernel (512 threads/block) ----------------
// blocks 0..511: queue->image | 512..527: q->image | 528..655: loss1 | 656: zero E/W
__global__ __launch_bounds__(512) void pre_kernel(const float* __restrict__ q,
                                                  const float* __restrict__ k,
                                                  const float* __restrict__ queue) {
    const int bid = blockIdx.x, tid = threadIdx.x;
    if (bid < 512) {
        // thread owns an n-pair (2np, 2np+1) x 8 kp values; float2 loads (coalesced 256B/warp)
        const int t = bid;
        const int np = tid & 63, kseg = tid >> 6;      // kseg 0..7 -> kp in [kseg*8, kseg*8+8)
        const float* qb = queue + (size_t)(kseg * 16) * KK + t * 128 + 2 * np;
        uint32_t v0[8], v1[8];
        #pragma unroll
        for (int kk = 0; kk < 8; kk++) {
            float2 x0 = *(const float2*)(qb + (size_t)(2 * kk) * KK);      // k even
            float2 x1 = *(const float2*)(qb + (size_t)(2 * kk + 1) * KK);  // k odd
            __nv_bfloat162 b0 = __floats2bfloat162_rn(x0.x, x1.x);         // row 2np
            __nv_bfloat162 b1 = __floats2bfloat162_rn(x0.y, x1.y);         // row 2np+1
            v0[kk] = *(uint32_t*)&b0;
            v1[kk] = *(uint32_t*)&b1;
        }
        uint32_t* dst = g_qu + (size_t)t * TILE_U32;
        uint32_t n0 = 2u * np, kp0 = (uint32_t)(kseg * 8);
        *(uint4*)(dst + tidx(n0, kp0))         = make_uint4(v0[0], v0[1], v0[2], v0[3]);
        *(uint4*)(dst + tidx(n0, kp0 + 4))     = make_uint4(v0[4], v0[5], v0[6], v0[7]);
        *(uint4*)(dst + tidx(n0 + 1, kp0))     = make_uint4(v1[0], v1[1], v1[2], v1[3]);
        *(uint4*)(dst + tidx(n0 + 1, kp0 + 4)) = make_uint4(v1[4], v1[5], v1[6], v1[7]);
    } else if (bid < 528) {
        // q -> bf16 swizzled tile image (tile = v*8+rb), natural [m][k] layout
        const int t = bid - 512;
        const float* src = q + (size_t)t * 128 * DD;
        uint32_t* dst = g_qt + (size_t)t * TILE_U32;
        #pragma unroll
        for (int it = 0; it < 16; it++) {
            int idx = it * 512 + tid;
            int row = idx >> 6, kp = idx & 63;
            float2 v = *(const float2*)(src + row * DD + 2 * kp);
            __nv_bfloat162 b = __floats2bfloat162_rn(v.x, v.y);
            dst[tidx(row, kp)] = *(uint32_t*)&b;
        }
    } else if (bid < 656) {
        // loss1 partial: 16 warps, warp per row; lane holds one float4
        __shared__ float sw[16];
        const int wid = tid >> 5, lane = tid & 31;
        const int w = (bid - 528) * 16 + wid;
        const int x = w >> 10, i = w & (NN - 1);
        float4 a = ((const float4*)(q + ((size_t)x * NN + i) * DD))[lane];
        float4 b = ((const float4*)(k + ((size_t)(1 - x) * NN + i) * DD))[lane];
        float dx = a.x - b.x, dy = a.y - b.y, dz = a.z - b.z, dw = a.w - b.w;
        float s = fmaf(dx, dx, fmaf(dy, dy, fmaf(dz, dz, dw * dw)));
        #pragma unroll
        for (int m = 16; m >= 1; m >>= 1) s += __shfl_xor_sync(0xffffffffu, s, m);
        if (lane == 0) sw[wid] = s;
        __syncthreads();
        if (tid == 0) {
            float acc = 0.f;
            #pragma unroll
            for (int j = 0; j < 16; j++) acc += sw[j];
            g_l1part[bid - 528] = acc;
        }
    } else {
        for (int i = tid; i < NV * NN; i += 512) {
            if (i < NN) { g_EQ[i] = 0.f; g_WQ[i] = 0.f; }
            g_EI[i] = 0.f; g_WI[i] = 0.f;
        }
    }
}

// ---------------- bf16 mma.sync GEMM, ping-pong halves, fused epilogue (R5 config) ---------
// bid < 512: queue part: rows = q[0] block (bid>>6), B tiles = j-group (bid&63)*8
// bid >= 512: intra part: view x, row block rb; B tiles = all 8 tiles of q[x]
__global__ __launch_bounds__(256, 2) void gemm_ws() {
    extern __shared__ __align__(128) char smg[];
    const uint32_t sb = smem_u32(smg);
    const uint32_t o_A = sb, o_B0 = sb + 32768, o_B1 = sb + 65536;
    const int tid = threadIdx.x, lane = tid & 31, wid = tid >> 5;
    const int wm = wid >> 1, wn = wid & 1;        // 4x2 warps, warp tile 32x64
    const int bid = blockIdx.x;

    const uint32_t *Asrc, *Bsrc;
    float *Eout, *Wout;
    int rowbase;
    if (bid < 512) {
        int rb = bid >> 6, jg = bid & 63;
        Asrc = g_qt + (size_t)rb * TILE_U32;                  // view 0 rows
        Bsrc = g_qu + (size_t)(jg * 8) * TILE_U32;
        Eout = g_EQ; Wout = g_WQ; rowbase = rb * 128;
    } else {
        int id = bid - 512, x = id >> 3, rb = id & 7;
        Asrc = g_qt + (size_t)(x * 8 + rb) * TILE_U32;
        Bsrc = g_qt + (size_t)(x * 8) * TILE_U32;
        Eout = g_EI + x * NN; Wout = g_WI + x * NN; rowbase = rb * 128;
    }

    // prologue: A + B0 (contiguous 32KB copies), one commit group
    #pragma unroll
    for (int c = 0; c < 8; c++) cp16(o_A + (c * 256 + tid) * 16, Asrc + (c * 256 + tid) * 4);
    #pragma unroll
    for (int c = 0; c < 8; c++) cp16(o_B0 + (c * 256 + tid) * 16, Bsrc + (c * 256 + tid) * 4);
    asm volatile("cp.async.commit_group;");

    // per-lane ldmatrix address components
    const uint32_t swz = (uint32_t)(lane & 7);
    const uint32_t hiA = (uint32_t)(lane >> 4);
    const uint32_t baseA0 = o_A + (uint32_t)(wm * 32 + (lane & 15)) * 256u;
    const uint32_t baseA1 = baseA0 + 4096u;      // +16 rows
    const uint32_t nrowb = (uint32_t)(wn * 64 + ((lane >> 4) & 1) * 8 + (lane & 7));
    const uint32_t kbB = (uint32_t)((lane >> 3) & 1);

    float accA[32], accB[32];
    #pragma unroll
    for (int i = 0; i < 32; i++) { accA[i] = 0.f; accB[i] = 0.f; }
    float E[4] = {0.f, 0.f, 0.f, 0.f}, W[4] = {0.f, 0.f, 0.f, 0.f};

    for (int t = 0; t < 8; t++) {
        const int buf = t & 1;
        if (t < 7) {          // prefetch next B into the other buffer
            uint32_t dstB = buf ? o_B0 : o_B1;
            const uint32_t* s = Bsrc + (size_t)(t + 1) * TILE_U32;
            #pragma unroll
            for (int c = 0; c < 8; c++) cp16(dstB + (c * 256 + tid) * 16, s + (c * 256 + tid) * 4);
            asm volatile("cp.async.commit_group;");
            asm volatile("cp.async.wait_group 1;");
        } else {
            asm volatile("cp.async.wait_group 0;");
        }
        __syncthreads();      // current B visible to all warps

        const uint32_t Brow = (buf ? o_B1 : o_B0) + nrowb * 256u;
        // phase0: MMA half0 -> accA, overlapped with epilogue of accB (prev tile)
        if (t == 0) half_mma<0, false>(baseA0, baseA1, Brow, hiA, swz, kbB, accA, accB, E, W);
        else        half_mma<0, true >(baseA0, baseA1, Brow, hiA, swz, kbB, accA, accB, E, W);
        // phase1: MMA half1 -> accB, overlapped with epilogue of accA (this tile)
        half_mma<2, true>(baseA0, baseA1, Brow, hiA, swz, kbB, accB, accA, E, W);
        __syncthreads();      // all warps done reading B[t] before overwrite
    }
    #pragma unroll
    for (int f = 0; f < 32; f += 4) epi4(accB, f, E, W);   // drain last half

    // reduce over the 4 lanes sharing each row, then atomics
    #pragma unroll
    for (int m = 1; m < 4; m <<= 1)
        #pragma unroll
        for (int ri = 0; ri < 4; ri++) {
            E[ri] += __shfl_xor_sync(0xffffffffu, E[ri], m);
            W[ri] += __shfl_xor_sync(0xffffffffu, W[ri], m);
        }
    if ((lane & 3) == 0) {
        int g = lane >> 2;
        #pragma unroll
        for (int mt = 0; mt < 2; mt++)
            #pragma unroll
            for (int h = 0; h < 2; h++) {
                int row = rowbase + wm * 32 + mt * 16 + 8 * h + g;
                atomicAdd(&Eout[row], E[mt * 2 + h]);
                atomicAdd(&Wout[row], W[mt * 2 + h]);
            }
    }
}

__global__ void finalize_kernel(float* __restrict__ out) {
    int i = threadIdx.x;   // 1024 threads
    float v = 0.f;
    #pragma unroll
    for (int x = 0; x < NV; x++) {
        float S  = g_EQ[i] + g_EI[x * NN + i];   // sum e^{-s} incl. diagonal (=1)
        float Wt = g_WQ[i] + g_WI[x * NN + i];   // sum d*e^{-s}
        float T = 2.f * (S - Wt);                // sum s*e^{-s} (diag adds 0)
        float E = S - 1.f;                       // drop diagonal
        v -= T / E;
    }
    float l1 = (i < 128) ? g_l1part[i] : 0.f;
    __shared__ float r2[32], r1[32];
    #pragma unroll
    for (int m = 16; m >= 1; m >>= 1) {
        v  += __shfl_xor_sync(0xffffffffu, v, m);
        l1 += __shfl_xor_sync(0xffffffffu, l1, m);
    }
    if ((i & 31) == 0) { r2[i >> 5] = v; r1[i >> 5] = l1; }
    __syncthreads();
    if (i < 32) {
        float w = r2[i], u = r1[i];
        #pragma unroll
        for (int m = 16; m >= 1; m >>= 1) {
            w += __shfl_xor_sync(0xffffffffu, w, m);
            u += __shfl_xor_sync(0xffffffffu, u, m);
        }
        if (i == 0) {
            out[0] = u * (1.0f / (NV * NN));
            out[1] = w * (1.0f / (NV * NN));
        }
    }
}

// ---------------- launcher ----------------
extern "C" void kernel_launch(void* const* d_in, const int* in_sizes, int n_in,
                              void* d_out, int out_size) {
    const float* q     = (const float*)d_in[0];
    const float* k     = (const float*)d_in[1];
    const float* queue = (const float*)d_in[2];
    float* out = (float*)d_out;

    const int smem_gemm = 3 * 32768;              // A + B double buffer = 96KB
    cudaFuncSetAttribute(gemm_ws, cudaFuncAttributeMaxDynamicSharedMemorySize, smem_gemm);

    pre_kernel<<<657, 512>>>(q, k, queue);
    gemm_ws<<<512 + 16, 256, smem_gemm>>>();
    finalize_kernel<<<1, 1024>>>(out);
}

// round 8
// speedup vs baseline: 2.0587x; 1.0005x over previous
#include <cuda_runtime.h>
#include <cuda_bf16.h>
#include <cstdint>

// Problem: q [2,1024,128] (rows unit-norm), k [2,1024,128], queue [128,65536] (cols unit-norm)
#define NV 2
#define NN 1024
#define DD 128
#define KK 65536
#define QT 512              // queue tiles of 128 cols
#define TILE_U32 8192       // 32KB bf16 tile image (128 rows x 128 k, swizzled)

// ---------------- scratch (static device globals; no allocation) ----------------
__device__ __align__(128) uint32_t g_qu[QT * TILE_U32];       // queue tile images (16.8MB)
__device__ __align__(128) uint32_t g_qt[NV * 8 * TILE_U32];   // q tile images (512KB)
__device__ float g_EQ[NN], g_WQ[NN];          // queue part: sum e^{-s}, sum d*e^{-s}
__device__ float g_EI[NV * NN], g_WI[NV * NN];
__device__ float g_l1part[128];               // loss1 per-block partials

// ---------------- helpers ----------------
__device__ __forceinline__ uint32_t smem_u32(const void* p) {
    uint32_t a;
    asm("{ .reg .u64 t; cvta.to.shared.u64 t, %1; cvt.u32.u64 %0, t; }" : "=r"(a) : "l"(p));
    return a;
}
__device__ __forceinline__ void cp16(uint32_t daddr, const void* src) {
    asm volatile("cp.async.cg.shared.global [%0], [%1], 16;" :: "r"(daddr), "l"(src));
}
__device__ __forceinline__ void ldsm_x4(uint32_t* r, uint32_t addr) {
    asm volatile("ldmatrix.sync.aligned.m8n8.x4.shared.b16 {%0,%1,%2,%3}, [%4];"
                 : "=r"(r[0]), "=r"(r[1]), "=r"(r[2]), "=r"(r[3]) : "r"(addr));
}
__device__ __forceinline__ void mma_bf16(float* c, const uint32_t* a, const uint32_t* b) {
    asm volatile(
        "mma.sync.aligned.m16n8k16.row.col.f32.bf16.bf16.f32 "
        "{%0,%1,%2,%3}, {%4,%5,%6,%7}, {%8,%9}, {%0,%1,%2,%3};"
        : "+f"(c[0]), "+f"(c[1]), "+f"(c[2]), "+f"(c[3])
        : "r"(a[0]), "r"(a[1]), "r"(a[2]), "r"(a[3]), "r"(b[0]), "r"(b[1]));
}
// swizzled u32 index inside a 128x128 bf16 tile: row stride 256B, 16B chunks XOR (row&7)
__device__ __forceinline__ uint32_t tidx(uint32_t row, uint32_t kp /*k/2*/) {
    return row * 64u + ((((kp >> 2) ^ (row & 7u))) << 2) + (kp & 3u);
}

// epilogue of 4 accumulator elements (2 f16x2 ex2 pairs): w=e^{2d-2}; E+=w; W+=d*w; rezero
__device__ __forceinline__ void epi4(float* acc, int f0, float* E, float* W) {
    #pragma unroll
    for (int u = 0; u < 4; u += 2) {
        int f = f0 + u;
        float d0 = acc[f], d1 = acc[f + 1];
        acc[f] = 0.f; acc[f + 1] = 0.f;
        float e0 = fmaf(d0, 2.885390082f, -2.885390082f);   // (2d-2)*log2(e)
        float e1 = fmaf(d1, 2.885390082f, -2.885390082f);
        uint32_t hp;
        asm("cvt.rn.f16x2.f32 %0, %1, %2;" : "=r"(hp) : "f"(e1), "f"(e0));  // lo=e0, hi=e1
        asm("ex2.approx.f16x2 %0, %0;" : "+r"(hp));
        float w0, w1;
        asm("{ .reg .b16 l, h;\n\t mov.b32 {l, h}, %2;\n\t"
            "cvt.f32.f16 %0, l;\n\t cvt.f32.f16 %1, h; }"
            : "=f"(w0), "=f"(w1) : "r"(hp));
        int ri = ((f >> 4) << 1) + ((f & 3) >> 1);          // f and f+1 share ri
        E[ri] += w0 + w1;
        W[ri] = fmaf(d0, w0, fmaf(d1, w1, W[ri]));
    }
}

// MMA over one 32-col half (PBASE = 0 or 2), interleaving the epilogue of the OTHER half
template <int PBASE, bool DOEPI>
__device__ __forceinline__ void half_mma(uint32_t baseA0, uint32_t baseA1, uint32_t Brow,
                                         uint32_t hiA, uint32_t swz, uint32_t kbB,
                                         float* acc, float* oacc, float* E, float* W) {
    #pragma unroll
    for (int ks = 0; ks < 8; ks++) {
        uint32_t a0[4], a1[4];
        uint32_t offA = (((2u * (uint32_t)ks + hiA) ^ swz) << 4);
        ldsm_x4(a0, baseA0 + offA);
        ldsm_x4(a1, baseA1 + offA);
        uint32_t offB = (((2u * (uint32_t)ks + kbB) ^ swz) << 4);
        #pragma unroll
        for (int pp = 0; pp < 2; pp++) {
            uint32_t bb[4];
            ldsm_x4(bb, Brow + (uint32_t)((PBASE + pp) * 4096) + offB);
            mma_bf16(&acc[(2 * pp) * 4],          a0, bb);
            mma_bf16(&acc[(2 * pp + 1) * 4],      a0, bb + 2);
            mma_bf16(&acc[16 + (2 * pp) * 4],     a1, bb);
            mma_bf16(&acc[16 + (2 * pp + 1) * 4], a1, bb + 2);
        }
        if (DOEPI) epi4(oacc, ks * 4, E, W);
    }
}

// ---------------- merged pre-kernel (512 threads/block) ----------------
// blocks 0..511: queue->image | 512..527: q->image | 528..655: loss1 | 656: zero E/W
__global__ __launch_bounds__(512) void pre_kernel(const float* __restrict__ q,
                                                  const float* __restrict__ k,
                                                  const float* __restrict__ queue) {
    const int bid = blockIdx.x, tid = threadIdx.x;
    if (bid < 512) {
        // thread owns an n-pair (2np, 2np+1) x 8 kp values; float2 loads (coalesced 256B/warp)
        const int t = bid;
        const int np = tid & 63, kseg = tid >> 6;      // kseg 0..7 -> kp in [kseg*8, kseg*8+8)
        const float* qb = queue + (size_t)(kseg * 16) * KK + t * 128 + 2 * np;
        uint32_t v0[8], v1[8];
        #pragma unroll
        for (int kk = 0; kk < 8; kk++) {
            float2 x0 = *(const float2*)(qb + (size_t)(2 * kk) * KK);      // k even
            float2 x1 = *(const float2*)(qb + (size_t)(2 * kk + 1) * KK);  // k odd
            __nv_bfloat162 b0 = __floats2bfloat162_rn(x0.x, x1.x);         // row 2np
            __nv_bfloat162 b1 = __floats2bfloat162_rn(x0.y, x1.y);         // row 2np+1
            v0[kk] = *(uint32_t*)&b0;
            v1[kk] = *(uint32_t*)&b1;
        }
        uint32_t* dst = g_qu + (size_t)t * TILE_U32;
        uint32_t n0 = 2u * np, kp0 = (uint32_t)(kseg * 8);
        *(uint4*)(dst + tidx(n0, kp0))         = make_uint4(v0[0], v0[1], v0[2], v0[3]);
        *(uint4*)(dst + tidx(n0, kp0 + 4))     = make_uint4(v0[4], v0[5], v0[6], v0[7]);
        *(uint4*)(dst + tidx(n0 + 1, kp0))     = make_uint4(v1[0], v1[1], v1[2], v1[3]);
        *(uint4*)(dst + tidx(n0 + 1, kp0 + 4)) = make_uint4(v1[4], v1[5], v1[6], v1[7]);
    } else if (bid < 528) {
        // q -> bf16 swizzled tile image (tile = v*8+rb), natural [m][k] layout
        const int t = bid - 512;
        const float* src = q + (size_t)t * 128 * DD;
        uint32_t* dst = g_qt + (size_t)t * TILE_U32;
        #pragma unroll
        for (int it = 0; it < 16; it++) {
            int idx = it * 512 + tid;
            int row = idx >> 6, kp = idx & 63;
            float2 v = *(const float2*)(src + row * DD + 2 * kp);
            __nv_bfloat162 b = __floats2bfloat162_rn(v.x, v.y);
            dst[tidx(row, kp)] = *(uint32_t*)&b;
        }
    } else if (bid < 656) {
        // loss1 partial: 16 warps, warp per row; lane holds one float4
        __shared__ float sw[16];
        const int wid = tid >> 5, lane = tid & 31;
        const int w = (bid - 528) * 16 + wid;
        const int x = w >> 10, i = w & (NN - 1);
        float4 a = ((const float4*)(q + ((size_t)x * NN + i) * DD))[lane];
        float4 b = ((const float4*)(k + ((size_t)(1 - x) * NN + i) * DD))[lane];
        float dx = a.x - b.x, dy = a.y - b.y, dz = a.z - b.z, dw = a.w - b.w;
        float s = fmaf(dx, dx, fmaf(dy, dy, fmaf(dz, dz, dw * dw)));
        #pragma unroll
        for (int m = 16; m >= 1; m >>= 1) s += __shfl_xor_sync(0xffffffffu, s, m);
        if (lane == 0) sw[wid] = s;
        __syncthreads();
        if (tid == 0) {
            float acc = 0.f;
            #pragma unroll
            for (int j = 0; j < 16; j++) acc += sw[j];
            g_l1part[bid - 528] = acc;
        }
    } else {
        for (int i = tid; i < NV * NN; i += 512) {
            if (i < NN) { g_EQ[i] = 0.f; g_WQ[i] = 0.f; }
            g_EI[i] = 0.f; g_WI[i] = 0.f;
        }
    }
}

// ---------------- bf16 mma.sync GEMM, ping-pong halves, fused epilogue (R5 config) ---------
// bid < 512: queue part: rows = q[0] block (bid>>6), B tiles = j-group (bid&63)*8
// bid >= 512: intra part: view x, row block rb; B tiles = all 8 tiles of q[x]
__global__ __launch_bounds__(256, 2) void gemm_ws() {
    extern __shared__ __align__(128) char smg[];
    const uint32_t sb = smem_u32(smg);
    const uint32_t o_A = sb, o_B0 = sb + 32768, o_B1 = sb + 65536;
    const int tid = threadIdx.x, lane = tid & 31, wid = tid >> 5;
    const int wm = wid >> 1, wn = wid & 1;        // 4x2 warps, warp tile 32x64
    const int bid = blockIdx.x;

    const uint32_t *Asrc, *Bsrc;
    float *Eout, *Wout;
    int rowbase;
    if (bid < 512) {
        int rb = bid >> 6, jg = bid & 63;
        Asrc = g_qt + (size_t)rb * TILE_U32;                  // view 0 rows
        Bsrc = g_qu + (size_t)(jg * 8) * TILE_U32;
        Eout = g_EQ; Wout = g_WQ; rowbase = rb * 128;
    } else {
        int id = bid - 512, x = id >> 3, rb = id & 7;
        Asrc = g_qt + (size_t)(x * 8 + rb) * TILE_U32;
        Bsrc = g_qt + (size_t)(x * 8) * TILE_U32;
        Eout = g_EI + x * NN; Wout = g_WI + x * NN; rowbase = rb * 128;
    }

    // prologue: A + B0 (contiguous 32KB copies), one commit group
    #pragma unroll
    for (int c = 0; c < 8; c++) cp16(o_A + (c * 256 + tid) * 16, Asrc + (c * 256 + tid) * 4);
    #pragma unroll
    for (int c = 0; c < 8; c++) cp16(o_B0 + (c * 256 + tid) * 16, Bsrc + (c * 256 + tid) * 4);
    asm volatile("cp.async.commit_group;");

    // per-lane ldmatrix address components
    const uint32_t swz = (uint32_t)(lane & 7);
    const uint32_t hiA = (uint32_t)(lane >> 4);
    const uint32_t baseA0 = o_A + (uint32_t)(wm * 32 + (lane & 15)) * 256u;
    const uint32_t baseA1 = baseA0 + 4096u;      // +16 rows
    const uint32_t nrowb = (uint32_t)(wn * 64 + ((lane >> 4) & 1) * 8 + (lane & 7));
    const uint32_t kbB = (uint32_t)((lane >> 3) & 1);

    float accA[32], accB[32];
    #pragma unroll
    for (int i = 0; i < 32; i++) { accA[i] = 0.f; accB[i] = 0.f; }
    float E[4] = {0.f, 0.f, 0.f, 0.f}, W[4] = {0.f, 0.f, 0.f, 0.f};

    for (int t = 0; t < 8; t++) {
        const int buf = t & 1;
        if (t < 7) {          // prefetch next B into the other buffer
            uint32_t dstB = buf ? o_B0 : o_B1;
            const uint32_t* s = Bsrc + (size_t)(t + 1) * TILE_U32;
            #pragma unroll
            for (int c = 0; c < 8; c++) cp16(dstB + (c * 256 + tid) * 16, s + (c * 256 + tid) * 4);
            asm volatile("cp.async.commit_group;");
            asm volatile("cp.async.wait_group 1;");
        } else {
            asm volatile("cp.async.wait_group 0;");
        }
        __syncthreads();      // current B visible to all warps

        const uint32_t Brow = (buf ? o_B1 : o_B0) + nrowb * 256u;
        // phase0: MMA half0 -> accA, overlapped with epilogue of accB (prev tile)
        if (t == 0) half_mma<0, false>(baseA0, baseA1, Brow, hiA, swz, kbB, accA, accB, E, W);
        else        half_mma<0, true >(baseA0, baseA1, Brow, hiA, swz, kbB, accA, accB, E, W);
        // phase1: MMA half1 -> accB, overlapped with epilogue of accA (this tile)
        half_mma<2, true>(baseA0, baseA1, Brow, hiA, swz, kbB, accB, accA, E, W);
        __syncthreads();      // all warps done reading B[t] before overwrite
    }
    #pragma unroll
    for (int f = 0; f < 32; f += 4) epi4(accB, f, E, W);   // drain last half

    // reduce over the 4 lanes sharing each row, then atomics
    #pragma unroll
    for (int m = 1; m < 4; m <<= 1)
        #pragma unroll
        for (int ri = 0; ri < 4; ri++) {
            E[ri] += __shfl_xor_sync(0xffffffffu, E[ri], m);
            W[ri] += __shfl_xor_sync(0xffffffffu, W[ri], m);
        }
    if ((lane & 3) == 0) {
        int g = lane >> 2;
        #pragma unroll
        for (int mt = 0; mt < 2; mt++)
            #pragma unroll
            for (int h = 0; h < 2; h++) {
                int row = rowbase + wm * 32 + mt * 16 + 8 * h + g;
                atomicAdd(&Eout[row], E[mt * 2 + h]);
                atomicAdd(&Wout[row], W[mt * 2 + h]);
            }
    }
}

__global__ void finalize_kernel(float* __restrict__ out) {
    int i = threadIdx.x;   // 1024 threads
    float v = 0.f;
    #pragma unroll
    for (int x = 0; x < NV; x++) {
        float S  = g_EQ[i] + g_EI[x * NN + i];   // sum e^{-s} incl. diagonal (=1)
        float Wt = g_WQ[i] + g_WI[x * NN + i];   // sum d*e^{-s}
        float T = 2.f * (S - Wt);                // sum s*e^{-s} (diag adds 0)
        float E = S - 1.f;                       // drop diagonal
        v -= T / E;
    }
    float l1 = (i < 128) ? g_l1part[i] : 0.f;
    __shared__ float r2[32], r1[32];
    #pragma unroll
    for (int m = 16; m >= 1; m >>= 1) {
        v  += __shfl_xor_sync(0xffffffffu, v, m);
        l1 += __shfl_xor_sync(0xffffffffu, l1, m);
    }
    if ((i & 31) == 0) { r2[i >> 5] = v; r1[i >> 5] = l1; }
    __syncthreads();
    if (i < 32) {
        float w = r2[i], u = r1[i];
        #pragma unroll
        for (int m = 16; m >= 1; m >>= 1) {
            w += __shfl_xor_sync(0xffffffffu, w, m);
            u += __shfl_xor_sync(0xffffffffu, u, m);
        }
        if (i == 0) {
            out[0] = u * (1.0f / (NV * NN));
            out[1] = w * (1.0f / (NV * NN));
        }
    }
}

// ---------------- launcher ----------------
extern "C" void kernel_launch(void* const* d_in, const int* in_sizes, int n_in,
                              void* d_out, int out_size) {
    const float* q     = (const float*)d_in[0];
    const float* k     = (const float*)d_in[1];
    const float* queue = (const float*)d_in[2];
    float* out = (float*)d_out;

    const int smem_gemm = 3 * 32768;              // A + B double buffer = 96KB
    cudaFuncSetAttribute(gemm_ws, cudaFuncAttributeMaxDynamicSharedMemorySize, smem_gemm);

    pre_kernel<<<657, 512>>>(q, k, queue);
    gemm_ws<<<512 + 16, 256, smem_gemm>>>();
    finalize_kernel<<<1, 1024>>>(out);
}